// round 1
// baseline (speedup 1.0000x reference)
#include <cuda_runtime.h>
#include <math.h>

#define NUM_ENVS 16384
#define NUM_AGENTS 16
#define IN_DIM 128
#define GCN_H 64
#define RNN_H 64
#define E_PER_GRAPH 128
#define OUT_DIM 512               // 16*4*8
#define FLAT_H (NUM_AGENTS * RNN_H)   // 1024

// Scratch (static device globals — no allocation allowed)
__device__ float  g_hbuf[(size_t)NUM_ENVS * FLAT_H];   // h_new, [env][agent][64]
__device__ float2 g_Wpk[RNN_H * 3 * RNN_H];            // [k][192] interleaved (W_ihT, W_hhT)

// ---------------------------------------------------------------------------
// Pack W_ih [192,64] and W_hh [192,64] into Wpk[k*192+g] = (W_ih[g][k], W_hh[g][k])
// ---------------------------------------------------------------------------
__global__ void pack_w_kernel(const float* __restrict__ W_ih,
                              const float* __restrict__ W_hh) {
    int idx = blockIdx.x * 256 + threadIdx.x;
    if (idx < RNN_H * 192) {
        int k = idx / 192;
        int g = idx % 192;
        g_Wpk[idx] = make_float2(W_ih[g * RNN_H + k], W_hh[g * RNN_H + k]);
    }
}

__device__ __forceinline__ float sigf(float v) {
    return 1.0f / (1.0f + expf(-v));
}

// ---------------------------------------------------------------------------
// Fused per-env GCN + GRU. 1 env per block, 256 threads.
// ---------------------------------------------------------------------------
__global__ __launch_bounds__(256) void fused_gcn_gru(
    const float* __restrict__ x,          // [env,16,128]
    const int*   __restrict__ ei,         // [env,2,128]  (int32)
    const float* __restrict__ prev_h,     // [env,16,64]
    const float* __restrict__ Wg,         // [128,64]
    const float* __restrict__ bg,         // [64]
    const float* __restrict__ b_ih,       // [192]
    const float* __restrict__ b_hh,       // [192]
    float*       __restrict__ nh_out)     // [env,16,64] or nullptr
{
    __shared__ float  x_s[NUM_AGENTS * IN_DIM];      // 8 KB
    __shared__ float2 gh_s[NUM_AGENTS * RNN_H];      // 8 KB (.x=gcn_out, .y=prev_h)
    __shared__ float  xw_s[NUM_AGENTS * GCN_H];      // 4 KB
    __shared__ float  agg_s[NUM_AGENTS * 65];        // padded, 4.1 KB
    __shared__ int    row_s[E_PER_GRAPH], col_s[E_PER_GRAPH];
    __shared__ float  deg_s[NUM_AGENTS], dinv_s[NUM_AGENTS];

    const int env = blockIdx.x;
    const int t   = threadIdx.x;

    // ---- cooperative loads ----
    const float4* xe = (const float4*)(x + (size_t)env * (NUM_AGENTS * IN_DIM));
    #pragma unroll
    for (int i = 0; i < 2; i++)
        ((float4*)x_s)[t + i * 256] = xe[t + i * 256];

    const float* he = prev_h + (size_t)env * FLAT_H;
    #pragma unroll
    for (int i = 0; i < 4; i++)
        gh_s[t + i * 256].y = he[t + i * 256];

    const int* ee = ei + (size_t)env * (2 * E_PER_GRAPH);
    if (t < E_PER_GRAPH)      row_s[t] = ee[t];
    else                      col_s[t - E_PER_GRAPH] = ee[t];

    if (t < NUM_AGENTS) deg_s[t] = 1.0f;
    __syncthreads();

    // ---- degree ----
    if (t < E_PER_GRAPH) atomicAdd(&deg_s[col_s[t]], 1.0f);
    __syncthreads();
    if (t < NUM_AGENTS) dinv_s[t] = rsqrtf(deg_s[t]);

    const int j  = t & 63;
    const int rq = t >> 6;   // 0..3

    // ---- xw = x @ W_gcn  (4 rows per thread) ----
    {
        float a0 = 0.f, a1 = 0.f, a2 = 0.f, a3 = 0.f;
        #pragma unroll 8
        for (int k = 0; k < IN_DIM; k++) {
            float w = Wg[k * GCN_H + j];
            a0 += x_s[(rq     ) * IN_DIM + k] * w;
            a1 += x_s[(rq +  4) * IN_DIM + k] * w;
            a2 += x_s[(rq +  8) * IN_DIM + k] * w;
            a3 += x_s[(rq + 12) * IN_DIM + k] * w;
        }
        xw_s[(rq     ) * 64 + j] = a0;
        xw_s[(rq +  4) * 64 + j] = a1;
        xw_s[(rq +  8) * 64 + j] = a2;
        xw_s[(rq + 12) * 64 + j] = a3;
    }
    __syncthreads();

    // ---- self-loop init: agg = xw / deg ----
    #pragma unroll
    for (int i = 0; i < 4; i++) {
        int r = rq + 4 * i;
        agg_s[r * 65 + j] = xw_s[r * 64 + j] / deg_s[r];
    }
    __syncthreads();

    // ---- edge scatter: agg[col] += dinv[row]*dinv[col]*xw[row] ----
    #pragma unroll
    for (int i = 0; i < 32; i++) {
        int e  = rq + 4 * i;
        int rr = row_s[e];
        int cc = col_s[e];
        float v = dinv_s[rr] * dinv_s[cc] * xw_s[rr * 64 + j];
        atomicAdd(&agg_s[cc * 65 + j], v);
    }
    __syncthreads();

    // ---- gcn_out = agg + b_gcn → gh_s.x ----
    {
        float bgj = bg[j];
        #pragma unroll
        for (int i = 0; i < 4; i++) {
            int r = rq + 4 * i;
            gh_s[r * 64 + j].x = agg_s[r * 65 + j] + bgj;
        }
    }
    __syncthreads();

    // ---- GRU: 4 rows × 6 dots per thread ----
    float ar[4] = {0,0,0,0}, az[4] = {0,0,0,0}, an[4] = {0,0,0,0};
    float br[4] = {0,0,0,0}, bz[4] = {0,0,0,0}, bn_[4] = {0,0,0,0};
    #pragma unroll 4
    for (int k = 0; k < RNN_H; k++) {
        const float2* wp = g_Wpk + k * 192;
        float2 wr = wp[j];
        float2 wz = wp[64 + j];
        float2 wn = wp[128 + j];
        #pragma unroll
        for (int i = 0; i < 4; i++) {
            float2 gh = gh_s[(rq + 4 * i) * 64 + k];
            ar[i]  += gh.x * wr.x;  br[i]  += gh.y * wr.y;
            az[i]  += gh.x * wz.x;  bz[i]  += gh.y * wz.y;
            an[i]  += gh.x * wn.x;  bn_[i] += gh.y * wn.y;
        }
    }

    const float bihr = b_ih[j],       bhhr = b_hh[j];
    const float bihz = b_ih[64 + j],  bhhz = b_hh[64 + j];
    const float bihn = b_ih[128 + j], bhhn = b_hh[128 + j];

    float* hb = g_hbuf + (size_t)env * FLAT_H;
    #pragma unroll
    for (int i = 0; i < 4; i++) {
        int r = rq + 4 * i;
        float rg = sigf(ar[i] + br[i] + bihr + bhhr);
        float z  = sigf(az[i] + bz[i] + bihz + bhhz);
        float n  = tanhf(an[i] + bihn + rg * (bn_[i] + bhhn));
        float h  = gh_s[r * 64 + j].y;
        float hn = (1.0f - z) * n + z * h;
        hb[r * 64 + j] = hn;
        if (nh_out) nh_out[(size_t)env * FLAT_H + r * 64 + j] = hn;
    }
}

// ---------------------------------------------------------------------------
// logits = h_new_flat [16384,1024] @ W_lin^T [1024,512] + b_lin
// Tiled SGEMM: BM=128, BN=64, BK=16, 256 threads, 8x4 microtile.
// ---------------------------------------------------------------------------
#define BM 128
#define BN 64
#define BK 16

__global__ __launch_bounds__(256) void gemm512(
    const float* __restrict__ Wl,     // [512,1024] row-major (B, accessed as B[o][k])
    const float* __restrict__ bias,   // [512]
    float*       __restrict__ C)      // [16384,512]
{
    __shared__ float As[BK][BM + 4];   // padded: stride 132
    __shared__ float Bs[BK][BN + 4];   // padded: stride 68

    const int bm = blockIdx.y * BM;
    const int bn = blockIdx.x * BN;
    const int t  = threadIdx.x;
    const int tx = t & 15;     // 0..15 (N dir, x4)
    const int ty = t >> 4;     // 0..15 (M dir, x8)

    float acc[8][4];
    #pragma unroll
    for (int i = 0; i < 8; i++)
        #pragma unroll
        for (int jj = 0; jj < 4; jj++) acc[i][jj] = 0.0f;

    const float* A = g_hbuf;

    for (int k0 = 0; k0 < FLAT_H; k0 += BK) {
        // load A tile: 128 rows x 16 k = 512 float4, 2 per thread
        #pragma unroll
        for (int i = 0; i < 2; i++) {
            int id  = t + i * 256;
            int row = id >> 2;        // 0..127
            int kv  = id & 3;         // 0..3
            float4 v = *(const float4*)(A + (size_t)(bm + row) * FLAT_H + k0 + kv * 4);
            As[kv * 4 + 0][row] = v.x;
            As[kv * 4 + 1][row] = v.y;
            As[kv * 4 + 2][row] = v.z;
            As[kv * 4 + 3][row] = v.w;
        }
        // load B tile: 64 rows x 16 k = 256 float4, 1 per thread
        {
            int row = t >> 2;         // 0..63
            int kv  = t & 3;
            float4 v = *(const float4*)(Wl + (size_t)(bn + row) * FLAT_H + k0 + kv * 4);
            Bs[kv * 4 + 0][row] = v.x;
            Bs[kv * 4 + 1][row] = v.y;
            Bs[kv * 4 + 2][row] = v.z;
            Bs[kv * 4 + 3][row] = v.w;
        }
        __syncthreads();

        #pragma unroll
        for (int kk = 0; kk < BK; kk++) {
            float a[8], b[4];
            float4 a0 = *(const float4*)&As[kk][ty * 8];
            float4 a1 = *(const float4*)&As[kk][ty * 8 + 4];
            a[0]=a0.x; a[1]=a0.y; a[2]=a0.z; a[3]=a0.w;
            a[4]=a1.x; a[5]=a1.y; a[6]=a1.z; a[7]=a1.w;
            float4 b0 = *(const float4*)&Bs[kk][tx * 4];
            b[0]=b0.x; b[1]=b0.y; b[2]=b0.z; b[3]=b0.w;
            #pragma unroll
            for (int i = 0; i < 8; i++)
                #pragma unroll
                for (int jj = 0; jj < 4; jj++)
                    acc[i][jj] += a[i] * b[jj];
        }
        __syncthreads();
    }

    // epilogue: fused bias, float4 stores
    float4 bv = *(const float4*)(bias + bn + tx * 4);
    #pragma unroll
    for (int i = 0; i < 8; i++) {
        int row = bm + ty * 8 + i;
        float4 o;
        o.x = acc[i][0] + bv.x;
        o.y = acc[i][1] + bv.y;
        o.z = acc[i][2] + bv.z;
        o.w = acc[i][3] + bv.w;
        *(float4*)(C + (size_t)row * OUT_DIM + bn + tx * 4) = o;
    }
}

// ---------------------------------------------------------------------------
extern "C" void kernel_launch(void* const* d_in, const int* in_sizes, int n_in,
                              void* d_out, int out_size) {
    const float* x     = (const float*)d_in[0];
    const int*   ei    = (const int*)  d_in[1];   // jax default: int64 -> int32
    const float* ph    = (const float*)d_in[2];
    const float* Wg    = (const float*)d_in[3];
    const float* bg    = (const float*)d_in[4];
    const float* W_ih  = (const float*)d_in[5];
    const float* W_hh  = (const float*)d_in[6];
    const float* b_ih  = (const float*)d_in[7];
    const float* b_hh  = (const float*)d_in[8];
    const float* W_lin = (const float*)d_in[9];
    const float* b_lin = (const float*)d_in[10];

    float* out = (float*)d_out;
    // tuple output: [logits (16384*512) | next_h (16384*1024)]
    float* nh = (out_size >= NUM_ENVS * (OUT_DIM + FLAT_H))
                    ? out + (size_t)NUM_ENVS * OUT_DIM : nullptr;

    pack_w_kernel<<<48, 256>>>(W_ih, W_hh);
    fused_gcn_gru<<<NUM_ENVS, 256>>>(x, ei, ph, Wg, bg, b_ih, b_hh, nh);
    gemm512<<<dim3(OUT_DIM / BN, NUM_ENVS / BM), 256>>>(W_lin, b_lin, out);
}